// round 7
// baseline (speedup 1.0000x reference)
#include <cuda_runtime.h>
#include <cuda_bf16.h>

// Haar DWT (pywt 'haar', torch-style flipped filters + cross-correlation):
//   a=x[h,w] b=x[h,w+1] c=x[h+1,w] d=x[h+1,w+1]  (zero pad right/bottom)
//   LL=.5(a+b+c+d)  LH=.5(a+b-c-d)  HL=.5(a-b+c-d)  HH=.5(a-b-c+d)
// out[b, 4c+k, h, w]  ->  plane index 4*(b*C+c)+k
//
// R7: R3 shape (warp-per-row, dual column group, MLP=4 front-batched
// LDG.128, shuffle neighbors, 8x STG.128 all 512B/warp) but forced to
// 32 regs via __launch_bounds__(256,8) for 2048 thr/SM occupancy.

#define DWT_W 256
#define DWT_H 256
#define W4    (DWT_W / 4)
#define PLANE4 ((size_t)DWT_H * W4)
#define FULL  0xffffffffu

__device__ __forceinline__ void subbands_store(
    float4* __restrict__ ob, size_t oidx,
    float4 T, float4 B, float tn, float bn)
{
    const float ts0 = T.x + T.y, ts1 = T.y + T.z, ts2 = T.z + T.w, ts3 = T.w + tn;
    const float td0 = T.x - T.y, td1 = T.y - T.z, td2 = T.z - T.w, td3 = T.w - tn;
    const float bs0 = B.x + B.y, bs1 = B.y + B.z, bs2 = B.z + B.w, bs3 = B.w + bn;
    const float bd0 = B.x - B.y, bd1 = B.y - B.z, bd2 = B.z - B.w, bd3 = B.w - bn;

    float4 v;
    v.x = 0.5f * (ts0 + bs0); v.y = 0.5f * (ts1 + bs1);
    v.z = 0.5f * (ts2 + bs2); v.w = 0.5f * (ts3 + bs3);
    __stcs(ob + oidx, v);                                   // LL

    v.x = 0.5f * (ts0 - bs0); v.y = 0.5f * (ts1 - bs1);
    v.z = 0.5f * (ts2 - bs2); v.w = 0.5f * (ts3 - bs3);
    __stcs(ob + PLANE4 + oidx, v);                          // LH

    v.x = 0.5f * (td0 + bd0); v.y = 0.5f * (td1 + bd1);
    v.z = 0.5f * (td2 + bd2); v.w = 0.5f * (td3 + bd3);
    __stcs(ob + 2 * PLANE4 + oidx, v);                      // HL

    v.x = 0.5f * (td0 - bd0); v.y = 0.5f * (td1 - bd1);
    v.z = 0.5f * (td2 - bd2); v.w = 0.5f * (td3 - bd3);
    __stcs(ob + 3 * PLANE4 + oidx, v);                      // HH
}

// block (32, 8): one warp per row, 8 rows per block. grid: (H/8, B*C)
__global__ __launch_bounds__(256, 8)
void haar_dwt_kernel(const float* __restrict__ x, float* __restrict__ out)
{
    const int lane = threadIdx.x;                 // 0..31
    const int h    = blockIdx.x * 8 + threadIdx.y;
    const int bc   = blockIdx.y;

    const float4* xp4 = (const float4*)(x + (size_t)bc * DWT_H * DWT_W);
    const float4* rt  = xp4 + h * W4;

    // ---- front-batched loads: 4 independent 512B/warp LDG.128 (MLP=4) ----
    float4 t1 = rt[lane];            // cols [4*lane, 4*lane+4)
    float4 t2 = rt[lane + 32];       // cols [4*lane+128, ...)
    float4 u1, u2;
    if (h < DWT_H - 1) {
        const float4* ru = rt + W4;
        u1 = ru[lane];
        u2 = ru[lane + 32];
    } else {
        u1 = make_float4(0.f, 0.f, 0.f, 0.f);
        u2 = u1;
    }

    // ---- horizontal neighbors via shuffle (no extra LDGs) ----
    float nt1 = __shfl_down_sync(FULL, t1.x, 1);   // lane l: col 4l+4
    float nu1 = __shfl_down_sync(FULL, u1.x, 1);
    float nt2 = __shfl_down_sync(FULL, t2.x, 1);   // lane l: col 4l+132
    float nu2 = __shfl_down_sync(FULL, u2.x, 1);
    const float t2x0 = __shfl_sync(FULL, t2.x, 0); // col 128 (for g1 lane 31)
    const float u2x0 = __shfl_sync(FULL, u2.x, 0);
    if (lane == 31) {
        nt1 = t2x0;            // col 128
        nu1 = u2x0;
        nt2 = 0.f;             // col 256 -> zero pad
        nu2 = 0.f;
    }

    float4* ob = (float4*)out + (size_t)(4 * bc) * PLANE4;
    const size_t o1 = (size_t)h * W4 + lane;

    subbands_store(ob, o1,      t1, u1, nt1, nu1);   // group 1: cols [0,128)
    subbands_store(ob, o1 + 32, t2, u2, nt2, nu2);   // group 2: cols [128,256)
}

extern "C" void kernel_launch(void* const* d_in, const int* in_sizes, int n_in,
                              void* d_out, int out_size)
{
    const float* x = (const float*)d_in[0];
    float* out = (float*)d_out;

    const int n_planes = in_sizes[0] / (DWT_H * DWT_W);   // B*C = 512

    dim3 block(32, 8, 1);
    dim3 grid(DWT_H / 8, n_planes, 1);
    haar_dwt_kernel<<<grid, block>>>(x, out);
}

// round 10
// speedup vs baseline: 1.0178x; 1.0178x over previous
#include <cuda_runtime.h>
#include <cuda_bf16.h>

// Haar DWT (pywt 'haar', torch-style flipped filters + cross-correlation):
//   a=x[h,w] b=x[h,w+1] c=x[h+1,w] d=x[h+1,w+1]  (zero pad right/bottom)
//   LL=.5(a+b+c+d)  LH=.5(a+b-c-d)  HL=.5(a-b+c-d)  HH=.5(a-b-c+d)
// out[b, 4c+k, h, w]  ->  plane index 4*(b*C+c)+k
//
// R9 == R8 resubmit (prior round hit a container-level infra failure; the
// kernel never executed). R6 shape (warp = row x half-row, shuffle
// neighbors, 2x LDG.128 + 4x STG.128 per thread, all 512B/warp) with
// 128-thread blocks for finer CTA granularity (65536 blocks) -> smaller
// wave tails / less cross-CTA spread.

#define DWT_W 256
#define DWT_H 256
#define W4    (DWT_W / 4)
#define PLANE4 ((size_t)DWT_H * W4)
#define FULL  0xffffffffu

// block (32, 4): 4 warps = 2 rows x 2 column groups. grid: (H/2, B*C)
__global__ __launch_bounds__(128)
void haar_dwt_kernel(const float* __restrict__ x, float* __restrict__ out)
{
    const int lane = threadIdx.x;                 // 0..31
    const int g    = threadIdx.y & 1;             // column group: 0 -> [0,128), 1 -> [128,256)
    const int h    = blockIdx.x * 2 + (threadIdx.y >> 1);   // output row
    const int bc   = blockIdx.y;                  // b*C + c

    const float*  xp  = x + (size_t)bc * DWT_H * DWT_W;
    const float4* xp4 = (const float4*)xp;

    const int  col4    = 32 * g + lane;           // float4 column 0..63
    const bool has_bot = (h < DWT_H - 1);

    // ---- front-batched loads: 2 independent 512B/warp LDG.128 ----
    float4 top = xp4[h * W4 + col4];
    float4 bot = has_bot ? xp4[(h + 1) * W4 + col4]
                         : make_float4(0.f, 0.f, 0.f, 0.f);

    // ---- horizontal neighbors via shuffle; seam handled by lane 31 ----
    float tn = __shfl_down_sync(FULL, top.x, 1);
    float bn = __shfl_down_sync(FULL, bot.x, 1);
    if (lane == 31) {
        if (g == 0) {           // neighbor is col 128 (first elem of group 1)
            tn = __ldg(&xp[h * DWT_W + 128]);
            bn = has_bot ? __ldg(&xp[(h + 1) * DWT_W + 128]) : 0.0f;
        } else {                // neighbor is col 256 -> zero pad
            tn = 0.0f;
            bn = 0.0f;
        }
    }

    // ---- horizontal sums/diffs shared by the 4 subbands ----
    const float ts0 = top.x + top.y, ts1 = top.y + top.z, ts2 = top.z + top.w, ts3 = top.w + tn;
    const float td0 = top.x - top.y, td1 = top.y - top.z, td2 = top.z - top.w, td3 = top.w - tn;
    const float bs0 = bot.x + bot.y, bs1 = bot.y + bot.z, bs2 = bot.z + bot.w, bs3 = bot.w + bn;
    const float bd0 = bot.x - bot.y, bd1 = bot.y - bot.z, bd2 = bot.z - bot.w, bd3 = bot.w - bn;

    float4* ob = (float4*)out + (size_t)(4 * bc) * PLANE4;
    const size_t oidx = (size_t)h * W4 + col4;

    float4 v;
    v.x = 0.5f * (ts0 + bs0); v.y = 0.5f * (ts1 + bs1);
    v.z = 0.5f * (ts2 + bs2); v.w = 0.5f * (ts3 + bs3);
    __stcs(ob + oidx, v);                                   // LL

    v.x = 0.5f * (ts0 - bs0); v.y = 0.5f * (ts1 - bs1);
    v.z = 0.5f * (ts2 - bs2); v.w = 0.5f * (ts3 - bs3);
    __stcs(ob + PLANE4 + oidx, v);                          // LH

    v.x = 0.5f * (td0 + bd0); v.y = 0.5f * (td1 + bd1);
    v.z = 0.5f * (td2 + bd2); v.w = 0.5f * (td3 + bd3);
    __stcs(ob + 2 * PLANE4 + oidx, v);                      // HL

    v.x = 0.5f * (td0 - bd0); v.y = 0.5f * (td1 - bd1);
    v.z = 0.5f * (td2 - bd2); v.w = 0.5f * (td3 - bd3);
    __stcs(ob + 3 * PLANE4 + oidx, v);                      // HH
}

extern "C" void kernel_launch(void* const* d_in, const int* in_sizes, int n_in,
                              void* d_out, int out_size)
{
    const float* x = (const float*)d_in[0];
    float* out = (float*)d_out;

    const int n_planes = in_sizes[0] / (DWT_H * DWT_W);   // B*C = 512

    dim3 block(32, 4, 1);
    dim3 grid(DWT_H / 2, n_planes, 1);
    haar_dwt_kernel<<<grid, block>>>(x, out);
}